// round 10
// baseline (speedup 1.0000x reference)
#include <cuda_runtime.h>
#include <cuda_fp16.h>
#include <math.h>

// Masked SDPA, fp16 mma.sync.m16n8k16 flash attention.
// fp32->fp16 pre-pass (Q pre-scaled by 1/sqrt(d), exact); main kernel:
// cp.async double-buffered K/V + distance-1 register pipeline for the mask.
// B=16, To=Ti=2048, d=64. CTA: 128 thr (4 warps), 64x64 tiles.

namespace {

constexpr int TO = 2048;
constexpr int TI = 2048;
constexpr int DD = 64;
constexpr int BM = 64;
constexpr int BN = 64;
constexpr int NT = TI / BN;             // 32 tiles
constexpr int NEL = 16 * 2048 * 64;
constexpr int STH = 72;                 // smem row stride (halves)
constexpr int TILE_H = BN * STH;        // 4608 halves
constexpr int SMEM_BYTES = 4 * TILE_H * 2;   // 36864 B
constexpr float NEG = 1e10f;

__device__ __half g_qh[NEL];
__device__ __half g_kh[NEL];
__device__ __half g_vh[NEL];

__global__ __launch_bounds__(256)
void f2h_all(const float* __restrict__ q, const float* __restrict__ k,
             const float* __restrict__ v) {
    const int which = blockIdx.y;
    const float* src = (which == 0) ? q : (which == 1) ? k : v;
    __half* dst = (which == 0) ? g_qh : (which == 1) ? g_kh : g_vh;
    const float scale = (which == 0) ? 0.125f : 1.0f;   // 1/sqrt(64), exact in fp16
    const int i = (blockIdx.x * 256 + threadIdx.x) * 8;
    if (i >= NEL) return;
    const float4 a = *reinterpret_cast<const float4*>(src + i);
    const float4 b = *reinterpret_cast<const float4*>(src + i + 4);
    __half2 h0 = __float22half2_rn(make_float2(a.x * scale, a.y * scale));
    __half2 h1 = __float22half2_rn(make_float2(a.z * scale, a.w * scale));
    __half2 h2 = __float22half2_rn(make_float2(b.x * scale, b.y * scale));
    __half2 h3 = __float22half2_rn(make_float2(b.z * scale, b.w * scale));
    uint4 o;
    o.x = *reinterpret_cast<unsigned*>(&h0);
    o.y = *reinterpret_cast<unsigned*>(&h1);
    o.z = *reinterpret_cast<unsigned*>(&h2);
    o.w = *reinterpret_cast<unsigned*>(&h3);
    *reinterpret_cast<uint4*>(reinterpret_cast<char*>(dst) + (size_t)i * 2) = o;
}

__device__ __forceinline__ void hmma(float c[4],
                                     unsigned a0, unsigned a1, unsigned a2, unsigned a3,
                                     unsigned b0, unsigned b1) {
    asm("mma.sync.aligned.m16n8k16.row.col.f32.f16.f16.f32 "
        "{%0,%1,%2,%3},{%4,%5,%6,%7},{%8,%9},{%0,%1,%2,%3};"
        : "+f"(c[0]), "+f"(c[1]), "+f"(c[2]), "+f"(c[3])
        : "r"(a0), "r"(a1), "r"(a2), "r"(a3), "r"(b0), "r"(b1));
}

__device__ __forceinline__ void ldsm4(unsigned& a, unsigned& b, unsigned& c, unsigned& d,
                                      unsigned addr) {
    asm volatile("ldmatrix.sync.aligned.m8n8.x4.shared.b16 {%0,%1,%2,%3}, [%4];"
                 : "=r"(a), "=r"(b), "=r"(c), "=r"(d) : "r"(addr));
}

__device__ __forceinline__ void ldsm4t(unsigned& a, unsigned& b, unsigned& c, unsigned& d,
                                       unsigned addr) {
    asm volatile("ldmatrix.sync.aligned.m8n8.x4.trans.shared.b16 {%0,%1,%2,%3}, [%4];"
                 : "=r"(a), "=r"(b), "=r"(c), "=r"(d) : "r"(addr));
}

__device__ __forceinline__ void cp16(void* dst_smem, const void* src) {
    unsigned d = (unsigned)__cvta_generic_to_shared(dst_smem);
    asm volatile("cp.async.cg.shared.global [%0], [%1], 16;" :: "r"(d), "l"(src));
}

__device__ __forceinline__ unsigned packh2(float lo, float hi) {
    __half2 h = __float22half2_rn(make_float2(lo, hi));
    return *reinterpret_cast<unsigned*>(&h);
}

__global__ __launch_bounds__(128, 3)
void attn_fp16_kernel(const int* __restrict__ M, float* __restrict__ O)
{
    extern __shared__ __half sm[];
    __half* Kb0 = sm;
    __half* Kb1 = sm + TILE_H;
    __half* Vb0 = sm + 2 * TILE_H;
    __half* Vb1 = sm + 3 * TILE_H;

    const int tid  = threadIdx.x;
    const int lane = tid & 31;
    const int warp = tid >> 5;
    const int r0 = lane >> 2;
    const int jj = lane & 3;

    const int b  = blockIdx.y;
    const int q0 = blockIdx.x * BM;
    const int m0 = warp * 16;

    const __half* qh = g_qh + ((long)b * TO + q0) * DD;
    const __half* kh = g_kh + (long)b * TI * DD;
    const __half* vh = g_vh + (long)b * TI * DD;
    const int* mbA = M + ((long)((long)b * TO + q0 + m0 + r0)) * TI;
    const int* mbB = mbA + 8L * TI;

    // ---- mask tile 0 into registers (distance-1 pipeline; latency covered
    //      by the whole prologue below)
    int2 mskA[8], mskB[8];
    #pragma unroll
    for (int nt = 0; nt < 8; ++nt) {
        const int col = 8 * nt + 2 * jj;
        mskA[nt] = *reinterpret_cast<const int2*>(mbA + col);
        mskB[nt] = *reinterpret_cast<const int2*>(mbB + col);
    }

    // staging map: 128 threads cover 16 rows x 64 halves per pass
    const int sr = tid >> 3;
    const int sc = (tid & 7) << 3;

    const unsigned kfoff = ((((lane & 7) + (((lane >> 4) & 1) << 3)) * STH) +
                            (((lane >> 3) & 1) << 3)) * 2u;
    const unsigned vfoff = ((((lane & 7) + (((lane >> 3) & 1) << 3)) * STH) +
                            (((lane >> 4) & 1) << 3)) * 2u;
    const unsigned qfoff = (((m0 + (lane & 7) + (((lane >> 3) & 1) << 3)) * STH) +
                            (((lane >> 4) & 1) << 3)) * 2u;

    const unsigned kbu0 = (unsigned)__cvta_generic_to_shared(Kb0);
    const unsigned kbu1 = (unsigned)__cvta_generic_to_shared(Kb1);
    const unsigned vbu0 = (unsigned)__cvta_generic_to_shared(Vb0);
    const unsigned vbu1 = (unsigned)__cvta_generic_to_shared(Vb1);

    // ---- group A: Q tile -> Vb1 staging
    #pragma unroll
    for (int i = 0; i < 4; ++i) {
        const int r = sr + i * 16;
        cp16(Vb1 + r * STH + sc, qh + (long)r * DD + sc);
    }
    asm volatile("cp.async.commit_group;");

    // ---- group B: K/V tile 0
    #pragma unroll
    for (int i = 0; i < 4; ++i) {
        const int r = sr + i * 16;
        cp16(Kb0 + r * STH + sc, kh + (long)r * DD + sc);
        cp16(Vb0 + r * STH + sc, vh + (long)r * DD + sc);
    }
    asm volatile("cp.async.commit_group;");

    asm volatile("cp.async.wait_group 1;");   // Q resident
    __syncthreads();

    unsigned qa[4][4];
    #pragma unroll
    for (int c = 0; c < 4; ++c)
        ldsm4(qa[c][0], qa[c][1], qa[c][2], qa[c][3],
              (unsigned)__cvta_generic_to_shared(Vb1) + qfoff + (unsigned)(c * 16 * 2));
    __syncthreads();   // Vb1 free

    // ---- group C: K/V tile 1
    #pragma unroll
    for (int i = 0; i < 4; ++i) {
        const int r = sr + i * 16;
        cp16(Kb1 + r * STH + sc, kh + (long)(BN + r) * DD + sc);
        cp16(Vb1 + r * STH + sc, vh + (long)(BN + r) * DD + sc);
    }
    asm volatile("cp.async.commit_group;");

    float acc[8][4];
    #pragma unroll
    for (int dt = 0; dt < 8; ++dt)
        #pragma unroll
        for (int r = 0; r < 4; ++r) acc[dt][r] = 0.0f;

    float mA = -1e30f, mB = -1e30f, lA = 0.0f, lB = 0.0f;   // l: per-lane partials

    for (int t = 0; t < NT; ++t) {
        asm volatile("cp.async.wait_group 1;");
        __syncthreads();   // K/V tile t resident

        const unsigned kbu = (t & 1) ? kbu1 : kbu0;
        const unsigned vbu = (t & 1) ? vbu1 : vbu0;

        // ---- GEMM1: S = Q K^T  (Q pre-scaled by 1/sqrt(d))
        float s[8][4];
        #pragma unroll
        for (int nt = 0; nt < 8; ++nt)
            #pragma unroll
            for (int r = 0; r < 4; ++r) s[nt][r] = 0.0f;

        #pragma unroll
        for (int c = 0; c < 4; ++c) {
            #pragma unroll
            for (int p = 0; p < 4; ++p) {
                unsigned w0, w1, w2, w3;
                ldsm4(w0, w1, w2, w3,
                      kbu + kfoff + (unsigned)(((p * 16 * STH) + c * 16) * 2));
                hmma(s[2 * p],     qa[c][0], qa[c][1], qa[c][2], qa[c][3], w0, w1);
                hmma(s[2 * p + 1], qa[c][0], qa[c][1], qa[c][2], qa[c][3], w2, w3);
            }
        }

        // ---- mask apply (registers, selects only)
        #pragma unroll
        for (int nt = 0; nt < 8; ++nt) {
            s[nt][0] = mskA[nt].x ? s[nt][0] : -NEG;
            s[nt][1] = mskA[nt].y ? s[nt][1] : -NEG;
            s[nt][2] = mskB[nt].x ? s[nt][2] : -NEG;
            s[nt][3] = mskB[nt].y ? s[nt][3] : -NEG;
        }

        // ---- online softmax (max reduction only; l kept as per-lane partial)
        float tmA = -1e30f, tmB = -1e30f;
        #pragma unroll
        for (int nt = 0; nt < 8; ++nt) {
            tmA = fmaxf(tmA, fmaxf(s[nt][0], s[nt][1]));
            tmB = fmaxf(tmB, fmaxf(s[nt][2], s[nt][3]));
        }
        tmA = fmaxf(tmA, __shfl_xor_sync(0xffffffffu, tmA, 1));
        tmA = fmaxf(tmA, __shfl_xor_sync(0xffffffffu, tmA, 2));
        tmB = fmaxf(tmB, __shfl_xor_sync(0xffffffffu, tmB, 1));
        tmB = fmaxf(tmB, __shfl_xor_sync(0xffffffffu, tmB, 2));

        const float mnA = fmaxf(mA, tmA);
        const float mnB = fmaxf(mB, tmB);
        const float sfA = __expf(mA - mnA);
        const float sfB = __expf(mB - mnB);
        mA = mnA; mB = mnB;

        float psA = 0.0f, psB = 0.0f;
        #pragma unroll
        for (int nt = 0; nt < 8; ++nt) {
            s[nt][0] = __expf(s[nt][0] - mnA);
            s[nt][1] = __expf(s[nt][1] - mnA);
            s[nt][2] = __expf(s[nt][2] - mnB);
            s[nt][3] = __expf(s[nt][3] - mnB);
            psA += s[nt][0] + s[nt][1];
            psB += s[nt][2] + s[nt][3];
        }
        lA = lA * sfA + psA;       // per-lane partial; reduced at epilogue
        lB = lB * sfB + psB;

        #pragma unroll
        for (int dt = 0; dt < 8; ++dt) {
            acc[dt][0] *= sfA; acc[dt][1] *= sfA;
            acc[dt][2] *= sfB; acc[dt][3] *= sfB;
        }

        // ---- GEMM2: acc += P V  (C-frag == A-frag layout; just pack fp16)
        #pragma unroll
        for (int c = 0; c < 4; ++c) {
            const unsigned a0 = packh2(s[2 * c][0],     s[2 * c][1]);
            const unsigned a1 = packh2(s[2 * c][2],     s[2 * c][3]);
            const unsigned a2 = packh2(s[2 * c + 1][0], s[2 * c + 1][1]);
            const unsigned a3 = packh2(s[2 * c + 1][2], s[2 * c + 1][3]);
            #pragma unroll
            for (int p = 0; p < 4; ++p) {
                unsigned v0, v1, v2, v3;
                ldsm4t(v0, v1, v2, v3,
                       vbu + vfoff + (unsigned)(((c * 16 * STH) + p * 16) * 2));
                hmma(acc[2 * p],     a0, a1, a2, a3, v0, v1);
                hmma(acc[2 * p + 1], a0, a1, a2, a3, v2, v3);
            }
        }

        // ---- reload mask registers for tile t+1 (s[] dead here; covered by
        //      the sync + next tile's GEMM1)
        if (t + 1 < NT) {
            const int tcol = (t + 1) * BN;
            #pragma unroll
            for (int nt = 0; nt < 8; ++nt) {
                const int col = tcol + 8 * nt + 2 * jj;
                mskA[nt] = *reinterpret_cast<const int2*>(mbA + col);
                mskB[nt] = *reinterpret_cast<const int2*>(mbB + col);
            }
        }

        __syncthreads();   // all warps done with K/V buffer t&1

        // ---- prefetch K/V tile t+2 into buffer t&1
        if (t + 2 < NT) {
            __half* Kn = (t & 1) ? Kb1 : Kb0;
            __half* Vn = (t & 1) ? Vb1 : Vb0;
            const long off = (long)(t + 2) * BN;
            #pragma unroll
            for (int i = 0; i < 4; ++i) {
                const int r = sr + i * 16;
                cp16(Kn + r * STH + sc, kh + (off + r) * DD + sc);
                cp16(Vn + r * STH + sc, vh + (off + r) * DD + sc);
            }
        }
        asm volatile("cp.async.commit_group;");
    }

    // ---- epilogue: reduce l over quad, normalize, store
    lA += __shfl_xor_sync(0xffffffffu, lA, 1);
    lA += __shfl_xor_sync(0xffffffffu, lA, 2);
    lB += __shfl_xor_sync(0xffffffffu, lB, 1);
    lB += __shfl_xor_sync(0xffffffffu, lB, 2);
    const float invA = 1.0f / lA;
    const float invB = 1.0f / lB;
    float* oA = O + ((long)b * TO + q0 + m0 + r0) * DD;
    float* oB = oA + 8L * DD;
    #pragma unroll
    for (int dt = 0; dt < 8; ++dt) {
        const int c = 8 * dt + 2 * jj;
        float2 ra, rb;
        ra.x = acc[dt][0] * invA; ra.y = acc[dt][1] * invA;
        rb.x = acc[dt][2] * invB; rb.y = acc[dt][3] * invB;
        *reinterpret_cast<float2*>(oA + c) = ra;
        *reinterpret_cast<float2*>(oB + c) = rb;
    }
}

}  // namespace

extern "C" void kernel_launch(void* const* d_in, const int* in_sizes, int n_in,
                              void* d_out, int out_size)
{
    const float* q = (const float*)d_in[0];
    const float* k = (const float*)d_in[1];
    const float* v = (const float*)d_in[2];
    const int*   m = (const int*)d_in[3];
    float* out = (float*)d_out;

    dim3 cgrid(NEL / (256 * 8), 3);
    f2h_all<<<cgrid, 256>>>(q, k, v);

    dim3 grid(TO / BM, 16);
    dim3 block(128);
    attn_fp16_kernel<<<grid, block, SMEM_BYTES>>>(m, out);
}

// round 13
// speedup vs baseline: 1.6471x; 1.6471x over previous
#include <cuda_runtime.h>
#include <cuda_fp16.h>
#include <math.h>

// Masked SDPA, fp16 mma.sync.m16n8k16 flash attention.
// fp32->fp16 pre-pass (Q pre-scaled by 1/sqrt(d), exact).
// Main kernel: 3-stage cp.async K/V ring (one barrier per tile),
// L2-prefetched mask, deferred l-reduction.
// B=16, To=Ti=2048, d=64. CTA: 128 thr (4 warps), 64x64 tiles, 4 CTAs/SM.

namespace {

constexpr int TO = 2048;
constexpr int TI = 2048;
constexpr int DD = 64;
constexpr int BM = 64;
constexpr int BN = 64;
constexpr int NT = TI / BN;             // 32 tiles
constexpr int NEL = 16 * 2048 * 64;
constexpr int STH = 72;                 // smem row stride (halves)
constexpr int TILE_H = BN * STH;        // 4608 halves per K or V tile
constexpr int STAGE_H = 2 * TILE_H;     // K+V per stage (halves)
constexpr int STAGE_BYTES = STAGE_H * 2;      // 18432 B
constexpr int SMEM_BYTES = 3 * STAGE_BYTES;   // 55296 B
constexpr float NEG = 1e10f;

__device__ __half g_qh[NEL];
__device__ __half g_kh[NEL];
__device__ __half g_vh[NEL];

__global__ __launch_bounds__(256)
void f2h_all(const float* __restrict__ q, const float* __restrict__ k,
             const float* __restrict__ v) {
    const int which = blockIdx.y;
    const float* src = (which == 0) ? q : (which == 1) ? k : v;
    __half* dst = (which == 0) ? g_qh : (which == 1) ? g_kh : g_vh;
    const float scale = (which == 0) ? 0.125f : 1.0f;   // 1/sqrt(64), exact
    const int i = (blockIdx.x * 256 + threadIdx.x) * 8;
    if (i >= NEL) return;
    const float4 a = *reinterpret_cast<const float4*>(src + i);
    const float4 b = *reinterpret_cast<const float4*>(src + i + 4);
    __half2 h0 = __float22half2_rn(make_float2(a.x * scale, a.y * scale));
    __half2 h1 = __float22half2_rn(make_float2(a.z * scale, a.w * scale));
    __half2 h2 = __float22half2_rn(make_float2(b.x * scale, b.y * scale));
    __half2 h3 = __float22half2_rn(make_float2(b.z * scale, b.w * scale));
    uint4 o;
    o.x = *reinterpret_cast<unsigned*>(&h0);
    o.y = *reinterpret_cast<unsigned*>(&h1);
    o.z = *reinterpret_cast<unsigned*>(&h2);
    o.w = *reinterpret_cast<unsigned*>(&h3);
    *reinterpret_cast<uint4*>(reinterpret_cast<char*>(dst) + (size_t)i * 2) = o;
}

__device__ __forceinline__ void hmma(float c[4],
                                     unsigned a0, unsigned a1, unsigned a2, unsigned a3,
                                     unsigned b0, unsigned b1) {
    asm("mma.sync.aligned.m16n8k16.row.col.f32.f16.f16.f32 "
        "{%0,%1,%2,%3},{%4,%5,%6,%7},{%8,%9},{%0,%1,%2,%3};"
        : "+f"(c[0]), "+f"(c[1]), "+f"(c[2]), "+f"(c[3])
        : "r"(a0), "r"(a1), "r"(a2), "r"(a3), "r"(b0), "r"(b1));
}

__device__ __forceinline__ void ldsm4(unsigned& a, unsigned& b, unsigned& c, unsigned& d,
                                      unsigned addr) {
    asm volatile("ldmatrix.sync.aligned.m8n8.x4.shared.b16 {%0,%1,%2,%3}, [%4];"
                 : "=r"(a), "=r"(b), "=r"(c), "=r"(d) : "r"(addr));
}

__device__ __forceinline__ void ldsm4t(unsigned& a, unsigned& b, unsigned& c, unsigned& d,
                                       unsigned addr) {
    asm volatile("ldmatrix.sync.aligned.m8n8.x4.trans.shared.b16 {%0,%1,%2,%3}, [%4];"
                 : "=r"(a), "=r"(b), "=r"(c), "=r"(d) : "r"(addr));
}

__device__ __forceinline__ void cp16(void* dst_smem, const void* src) {
    unsigned d = (unsigned)__cvta_generic_to_shared(dst_smem);
    asm volatile("cp.async.cg.shared.global [%0], [%1], 16;" :: "r"(d), "l"(src));
}

__device__ __forceinline__ unsigned packh2(float lo, float hi) {
    __half2 h = __float22half2_rn(make_float2(lo, hi));
    return *reinterpret_cast<unsigned*>(&h);
}

__global__ __launch_bounds__(128, 4)
void attn_fp16_kernel(const int* __restrict__ M, float* __restrict__ O)
{
    extern __shared__ __half sm[];
    // stage s: K at sm + s*STAGE_H, V at sm + s*STAGE_H + TILE_H
    __half* Qstage = sm + 2 * STAGE_H + TILE_H;   // stage-2 V area (prologue only)

    const int tid  = threadIdx.x;
    const int lane = tid & 31;
    const int warp = tid >> 5;
    const int r0 = lane >> 2;
    const int jj = lane & 3;

    const int b  = blockIdx.y;
    const int q0 = blockIdx.x * BM;
    const int m0 = warp * 16;

    const __half* qh = g_qh + ((long)b * TO + q0) * DD;
    const __half* kh = g_kh + (long)b * TI * DD;
    const __half* vh = g_vh + (long)b * TI * DD;
    const int* mbA = M + ((long)((long)b * TO + q0 + m0 + r0)) * TI;
    const int* mbB = mbA + 8L * TI;

    // staging map: 128 threads cover 16 rows x 64 halves per pass
    const int sr = tid >> 3;
    const int sc = (tid & 7) << 3;

    const unsigned kfoff = ((((lane & 7) + (((lane >> 4) & 1) << 3)) * STH) +
                            (((lane >> 3) & 1) << 3)) * 2u;
    const unsigned vfoff = ((((lane & 7) + (((lane >> 3) & 1) << 3)) * STH) +
                            (((lane >> 4) & 1) << 3)) * 2u;
    const unsigned qfoff = (((m0 + (lane & 7) + (((lane >> 3) & 1) << 3)) * STH) +
                            (((lane >> 4) & 1) << 3)) * 2u;

    const unsigned smu = (unsigned)__cvta_generic_to_shared(sm);
    const unsigned qsu = (unsigned)__cvta_generic_to_shared(Qstage);

    // ---- group A: Q tile -> stage-2 V area
    #pragma unroll
    for (int i = 0; i < 4; ++i) {
        const int r = sr + i * 16;
        cp16(Qstage + r * STH + sc, qh + (long)r * DD + sc);
    }
    asm volatile("cp.async.commit_group;");

    // ---- group B: K/V tile 0 -> stage 0
    #pragma unroll
    for (int i = 0; i < 4; ++i) {
        const int r = sr + i * 16;
        cp16(sm + r * STH + sc, kh + (long)r * DD + sc);
        cp16(sm + TILE_H + r * STH + sc, vh + (long)r * DD + sc);
    }
    asm volatile("cp.async.commit_group;");

    asm volatile("cp.async.wait_group 1;");   // Q resident (B may fly)
    __syncthreads();

    unsigned qa[4][4];
    #pragma unroll
    for (int c = 0; c < 4; ++c)
        ldsm4(qa[c][0], qa[c][1], qa[c][2], qa[c][3],
              qsu + qfoff + (unsigned)(c * 16 * 2));

    // ---- group C: K/V tile 1 -> stage 1
    #pragma unroll
    for (int i = 0; i < 4; ++i) {
        const int r = sr + i * 16;
        cp16(sm + STAGE_H + r * STH + sc, kh + (long)(BN + r) * DD + sc);
        cp16(sm + STAGE_H + TILE_H + r * STH + sc, vh + (long)(BN + r) * DD + sc);
    }
    asm volatile("cp.async.commit_group;");

    float acc[8][4];
    #pragma unroll
    for (int dt = 0; dt < 8; ++dt)
        #pragma unroll
        for (int r = 0; r < 4; ++r) acc[dt][r] = 0.0f;

    float mA = -1e30f, mB = -1e30f, lA = 0.0f, lB = 0.0f;   // l: per-lane partials

    int st = 0;   // stage of tile t
    for (int t = 0; t < NT; ++t) {
        asm volatile("cp.async.wait_group 1;");
        __syncthreads();   // K/V tile t resident in stage st (ONLY barrier/tile)

        const unsigned kbu = smu + (unsigned)(st * STAGE_BYTES);
        const unsigned vbu = kbu + (unsigned)(TILE_H * 2);

        // ---- L2 prefetch of next tile's mask rows (zero reg cost)
        if (t + 1 < NT && jj < 2) {
            const int* pa = mbA + (t + 1) * BN + (jj << 5);
            const int* pb = mbB + (t + 1) * BN + (jj << 5);
            asm volatile("prefetch.global.L2 [%0];" :: "l"(pa));
            asm volatile("prefetch.global.L2 [%0];" :: "l"(pb));
        }

        // ---- GEMM1: S = Q K^T  (Q pre-scaled by 1/sqrt(d))
        float s[8][4];
        #pragma unroll
        for (int nt = 0; nt < 8; ++nt)
            #pragma unroll
            for (int r = 0; r < 4; ++r) s[nt][r] = 0.0f;

        #pragma unroll
        for (int c = 0; c < 4; ++c) {
            #pragma unroll
            for (int p = 0; p < 4; ++p) {
                unsigned w0, w1, w2, w3;
                ldsm4(w0, w1, w2, w3,
                      kbu + kfoff + (unsigned)(((p * 16 * STH) + c * 16) * 2));
                hmma(s[2 * p],     qa[c][0], qa[c][1], qa[c][2], qa[c][3], w0, w1);
                hmma(s[2 * p + 1], qa[c][0], qa[c][1], qa[c][2], qa[c][3], w2, w3);
            }
        }

        // ---- mask apply (LDG hits L2 thanks to prefetch)
        #pragma unroll
        for (int nt = 0; nt < 8; ++nt) {
            const int col = t * BN + 8 * nt + 2 * jj;
            const int2 ma  = *reinterpret_cast<const int2*>(mbA + col);
            const int2 mb2 = *reinterpret_cast<const int2*>(mbB + col);
            s[nt][0] = ma.x  ? s[nt][0] : -NEG;
            s[nt][1] = ma.y  ? s[nt][1] : -NEG;
            s[nt][2] = mb2.x ? s[nt][2] : -NEG;
            s[nt][3] = mb2.y ? s[nt][3] : -NEG;
        }

        // ---- online softmax (max reduction only; l stays per-lane)
        float tmA = -1e30f, tmB = -1e30f;
        #pragma unroll
        for (int nt = 0; nt < 8; ++nt) {
            tmA = fmaxf(tmA, fmaxf(s[nt][0], s[nt][1]));
            tmB = fmaxf(tmB, fmaxf(s[nt][2], s[nt][3]));
        }
        tmA = fmaxf(tmA, __shfl_xor_sync(0xffffffffu, tmA, 1));
        tmA = fmaxf(tmA, __shfl_xor_sync(0xffffffffu, tmA, 2));
        tmB = fmaxf(tmB, __shfl_xor_sync(0xffffffffu, tmB, 1));
        tmB = fmaxf(tmB, __shfl_xor_sync(0xffffffffu, tmB, 2));

        const float mnA = fmaxf(mA, tmA);
        const float mnB = fmaxf(mB, tmB);
        const float sfA = __expf(mA - mnA);
        const float sfB = __expf(mB - mnB);
        mA = mnA; mB = mnB;

        float psA = 0.0f, psB = 0.0f;
        #pragma unroll
        for (int nt = 0; nt < 8; ++nt) {
            s[nt][0] = __expf(s[nt][0] - mnA);
            s[nt][1] = __expf(s[nt][1] - mnA);
            s[nt][2] = __expf(s[nt][2] - mnB);
            s[nt][3] = __expf(s[nt][3] - mnB);
            psA += s[nt][0] + s[nt][1];
            psB += s[nt][2] + s[nt][3];
        }
        lA = lA * sfA + psA;
        lB = lB * sfB + psB;

        #pragma unroll
        for (int dt = 0; dt < 8; ++dt) {
            acc[dt][0] *= sfA; acc[dt][1] *= sfA;
            acc[dt][2] *= sfB; acc[dt][3] *= sfB;
        }

        // ---- GEMM2: acc += P V  (C-frag == A-frag layout; just pack fp16)
        #pragma unroll
        for (int c = 0; c < 4; ++c) {
            const unsigned a0 = packh2(s[2 * c][0],     s[2 * c][1]);
            const unsigned a1 = packh2(s[2 * c][2],     s[2 * c][3]);
            const unsigned a2 = packh2(s[2 * c + 1][0], s[2 * c + 1][1]);
            const unsigned a3 = packh2(s[2 * c + 1][2], s[2 * c + 1][3]);
            #pragma unroll
            for (int p = 0; p < 4; ++p) {
                unsigned v0, v1, v2, v3;
                ldsm4t(v0, v1, v2, v3,
                       vbu + vfoff + (unsigned)(((c * 16 * STH) + p * 16) * 2));
                hmma(acc[2 * p],     a0, a1, a2, a3, v0, v1);
                hmma(acc[2 * p + 1], a0, a1, a2, a3, v2, v3);
            }
        }

        // ---- prefetch K/V tile t+2 into stage (st+2)%3
        // Safe without a barrier: every warp already passed this tile's top
        // barrier, so no reader of that stage (tile t-1) is still active.
        if (t + 2 < NT) {
            int sn = st + 2; if (sn >= 3) sn -= 3;
            __half* Kn = sm + sn * STAGE_H;
            __half* Vn = Kn + TILE_H;
            const long off = (long)(t + 2) * BN;
            #pragma unroll
            for (int i = 0; i < 4; ++i) {
                const int r = sr + i * 16;
                cp16(Kn + r * STH + sc, kh + (off + r) * DD + sc);
                cp16(Vn + r * STH + sc, vh + (off + r) * DD + sc);
            }
        }
        asm volatile("cp.async.commit_group;");

        if (++st == 3) st = 0;
    }

    // ---- epilogue: reduce l over quad, normalize, store
    lA += __shfl_xor_sync(0xffffffffu, lA, 1);
    lA += __shfl_xor_sync(0xffffffffu, lA, 2);
    lB += __shfl_xor_sync(0xffffffffu, lB, 1);
    lB += __shfl_xor_sync(0xffffffffu, lB, 2);
    const float invA = 1.0f / lA;
    const float invB = 1.0f / lB;
    float* oA = O + ((long)b * TO + q0 + m0 + r0) * DD;
    float* oB = oA + 8L * DD;
    #pragma unroll
    for (int dt = 0; dt < 8; ++dt) {
        const int c = 8 * dt + 2 * jj;
        float2 ra, rb;
        ra.x = acc[dt][0] * invA; ra.y = acc[dt][1] * invA;
        rb.x = acc[dt][2] * invB; rb.y = acc[dt][3] * invB;
        *reinterpret_cast<float2*>(oA + c) = ra;
        *reinterpret_cast<float2*>(oB + c) = rb;
    }
}

}  // namespace

extern "C" void kernel_launch(void* const* d_in, const int* in_sizes, int n_in,
                              void* d_out, int out_size)
{
    const float* q = (const float*)d_in[0];
    const float* k = (const float*)d_in[1];
    const float* v = (const float*)d_in[2];
    const int*   m = (const int*)d_in[3];
    float* out = (float*)d_out;

    static bool attr_set = false;
    if (!attr_set) {
        cudaFuncSetAttribute(attn_fp16_kernel,
                             cudaFuncAttributeMaxDynamicSharedMemorySize,
                             SMEM_BYTES);
        attr_set = true;
    }

    dim3 cgrid(NEL / (256 * 8), 3);
    f2h_all<<<cgrid, 256>>>(q, k, v);

    dim3 grid(TO / BM, 16);
    dim3 block(128);
    attn_fp16_kernel<<<grid, block, SMEM_BYTES>>>(m, out);
}